// round 9
// baseline (speedup 1.0000x reference)
#include <cuda_runtime.h>
#include <math.h>
#include <stdint.h>

#define Nn 50000
#define Ee 640000
#define Dd 128
#define Hh 8
#define DHd 16
#define FFd 256
#define Cc 5
#define Ll 6
#define EPSf 1e-5f

#define SCAN_B 1024
#define SCAN_NB ((Nn + SCAN_B - 1) / SCAN_B)  // 49

// ---------------- scratch (device globals; no allocs allowed) ----------------
__device__ float g_q[Nn * Dd];
__device__ float g_k[Nn * Dd];
__device__ float g_v[Nn * Dd];
__device__ float g_attn[Nn * Dd];
__device__ float g_tmp1[Nn * Dd];
__device__ float g_tmp2[Nn * Dd];
__device__ float g_ff[Nn * FFd];
__device__ double g_sum1[Dd];
__device__ double g_sq1[Dd];
__device__ double g_sum2[Dd];
__device__ double g_sq2[Dd];
// CSR
__device__ int g_deg[Nn];
__device__ int g_cursor[Nn];
__device__ int g_rowptr[Nn + 1];
__device__ int g_scan[Nn];
__device__ int g_bsum[SCAN_NB];
__device__ int g_col[Ee];

// ---------------- tf32 / mma helpers (baseline PTX only) ----------------
__device__ __forceinline__ void tf32_split(float x, uint32_t& hi, uint32_t& lo) {
    uint32_t h;
    asm("cvt.rna.tf32.f32 %0, %1;" : "=r"(h) : "f"(x));
    float l = x - __uint_as_float(h);
    uint32_t lw;
    asm("cvt.rna.tf32.f32 %0, %1;" : "=r"(lw) : "f"(l));
    hi = h;
    lo = lw;
}

__device__ __forceinline__ void mma8(float* c, const uint32_t* a, const uint32_t* b) {
    asm volatile(
        "mma.sync.aligned.m16n8k8.row.col.f32.tf32.tf32.f32 "
        "{%0,%1,%2,%3}, {%4,%5,%6,%7}, {%8,%9}, {%0,%1,%2,%3};"
        : "+f"(c[0]), "+f"(c[1]), "+f"(c[2]), "+f"(c[3])
        : "r"(a[0]), "r"(a[1]), "r"(a[2]), "r"(a[3]), "r"(b[0]), "r"(b[1]));
}

#define LDSM_X4(R0, R1, R2, R3, ADDR)                                        \
    asm volatile("ldmatrix.sync.aligned.m8n8.x4.shared.b16 {%0,%1,%2,%3}, [%4];" \
                 : "=r"(R0), "=r"(R1), "=r"(R2), "=r"(R3) : "r"(ADDR))

// ---------------- CSR build ----------------
__global__ void csr_zero_kernel() {
    int i = blockIdx.x * blockDim.x + threadIdx.x;
    if (i < Nn) {
        g_deg[i] = 0;
        g_cursor[i] = 0;
    }
}

__global__ void csr_hist_kernel(const int* __restrict__ ei) {
    int e = blockIdx.x * blockDim.x + threadIdx.x;
    if (e < Ee) atomicAdd(&g_deg[ei[Ee + e]], 1);
}

__global__ void csr_scan1_kernel() {
    __shared__ int sh[SCAN_B];
    int gi = blockIdx.x * SCAN_B + threadIdx.x;
    int v = (gi < Nn) ? g_deg[gi] : 0;
    sh[threadIdx.x] = v;
    __syncthreads();
#pragma unroll
    for (int off = 1; off < SCAN_B; off <<= 1) {
        int t = (threadIdx.x >= off) ? sh[threadIdx.x - off] : 0;
        __syncthreads();
        sh[threadIdx.x] += t;
        __syncthreads();
    }
    if (gi < Nn) g_scan[gi] = sh[threadIdx.x];
    if (threadIdx.x == SCAN_B - 1) g_bsum[blockIdx.x] = sh[threadIdx.x];
}

__global__ void csr_scan23_kernel() {
    __shared__ int soff;
    if (threadIdx.x == 0) {
        int acc = 0;
        for (int i = 0; i < (int)blockIdx.x; i++) acc += g_bsum[i];
        soff = acc;
    }
    __syncthreads();
    int gi = blockIdx.x * SCAN_B + threadIdx.x;
    if (gi < Nn) g_rowptr[gi + 1] = g_scan[gi] + soff;
    if (gi == 0) g_rowptr[0] = 0;
}

__global__ void csr_scatter_kernel(const int* __restrict__ ei) {
    int e = blockIdx.x * blockDim.x + threadIdx.x;
    if (e >= Ee) return;
    int src = ei[e], dst = ei[Ee + e];
    int pos = g_rowptr[dst] + atomicAdd(&g_cursor[dst], 1);
    g_col[pos] = src;
}

__global__ void zero_stats_kernel(double* __restrict__ a, double* __restrict__ b) {
    int t = threadIdx.x;
    if (t < Dd) {
        a[t] = 0.0;
        b[t] = 0.0;
    }
}

// ---------------- warp-mma tf32 split-2 fused GEMM (ldmatrix + prefetch) ----
// C[M,NC] = op(A)[M,K] @ B[K,NC] (+bias)(+op(res))(relu). CTA tile 128x128,
// 8 warps (4 M x 2 N), warp tile 32x64, KC=16 chunks.
// A smem [m][k] pitch 20; B smem [n][k] pitch 20 (both ldmatrix-friendly,
// conflict-free). Register-staged prefetch of the next chunk.
template <int K, int NC, bool BIAS, bool RELU, bool RES, bool BNA, bool BNRES,
          bool STATS, int NMAT>
__global__ __launch_bounds__(256) void wm_gemm_kernel(
    const float* __restrict__ A,
    const float* __restrict__ B0, const float* __restrict__ B1, const float* __restrict__ B2,
    const float* __restrict__ bias, const float* __restrict__ res,
    const float* __restrict__ bng, const float* __restrict__ bnb,
    const double* __restrict__ bnsum, const double* __restrict__ bnsq,
    double* __restrict__ stsum, double* __restrict__ stsq,
    float* __restrict__ C0, float* __restrict__ C1, float* __restrict__ C2) {
    const int KC = 16;
    const int NCH = K / KC;
    const int YPM = NC / 128;
    constexpr int PSZ = BNA ? K : (BNRES ? 128 : 1);
    constexpr int SSZ = STATS ? 128 : 1;
    const int AP = 20;   // A smem pitch [m][k] (words)
    const int BP = 20;   // B smem pitch [n][k] (words)

    __shared__ uint32_t Ah[128 * AP], Al[128 * AP];
    __shared__ uint32_t Bh[128 * BP], Bl[128 * BP];
    __shared__ float s_sc[PSZ], s_sh[PSZ];
    __shared__ float s_cs[SSZ], s_cq[SSZ];

    int tid = threadIdx.x;
    int lane = tid & 31;
    int wid = tid >> 5;
    int wm = wid >> 1;   // 0..3
    int wn = wid & 1;    // 0..1
    int lr = lane >> 2;  // 0..7
    int lc = lane & 3;   // 0..3
    int rowBase = blockIdx.x * 128;
    int mat = (NMAT > 1) ? ((int)blockIdx.y / YPM) : 0;
    int colBase = ((int)blockIdx.y % YPM) * 128;
    const float* B = (NMAT > 1) ? (mat == 0 ? B0 : (mat == 1 ? B1 : B2)) : B0;
    float* C = (NMAT > 1) ? (mat == 0 ? C0 : (mat == 1 ? C1 : C2)) : C0;

    if (BNA || BNRES) {
        for (int c = tid; c < PSZ; c += 256) {
            double m = bnsum[c] / (double)Nn;
            double var = bnsq[c] / (double)Nn - m * m;
            float sc = rsqrtf((float)var + EPSf) * bng[c];
            s_sc[c] = sc;
            s_sh[c] = bnb[c] - (float)m * sc;
        }
        __syncthreads();
    }
    if (STATS) {
        if (tid < SSZ) {
            s_cs[tid] = 0.f;
            s_cq[tid] = 0.f;
        }
    }

    float acc[2][8][4];
#pragma unroll
    for (int i = 0; i < 2; i++)
#pragma unroll
        for (int j = 0; j < 8; j++)
#pragma unroll
            for (int t = 0; t < 4; t++) acc[i][j][t] = 0.f;

    // ---- fill-side per-thread coords ----
    const int ar = tid >> 2;          // A row 0..63 (l adds 64)
    const int ac = (tid & 3) * 4;     // A col 0,4,8,12
    const int bn = tid & 127;         // B n row
    const int bq0 = (tid >> 7) * 2;   // B k-quad base (0 or 2)

    // ---- ldmatrix per-thread addresses (byte, shared space) ----
    uint32_t ahB = (uint32_t)__cvta_generic_to_shared(Ah);
    uint32_t alB = (uint32_t)__cvta_generic_to_shared(Al);
    uint32_t bhB = (uint32_t)__cvta_generic_to_shared(Bh);
    uint32_t blB = (uint32_t)__cvta_generic_to_shared(Bl);
    const int aRow = (lane & 7) + ((lane >> 3) & 1) * 8;
    const int aK = ((lane >> 4) & 1) * 4;
    const int bRow = (lane & 7) + ((lane >> 4) & 1) * 8;
    const int bK = ((lane >> 3) & 1) * 4;
    uint32_t aOffH = ahB + (uint32_t)(((wm * 32 + aRow) * AP + aK) * 4);
    uint32_t aOffL = alB + (uint32_t)(((wm * 32 + aRow) * AP + aK) * 4);
    uint32_t bOffH = bhB + (uint32_t)(((wn * 64 + bRow) * BP + bK) * 4);
    uint32_t bOffL = blB + (uint32_t)(((wn * 64 + bRow) * BP + bK) * 4);

    float4 aReg[2];
    float bReg[8];

    auto load_regs = [&](int ch) {
        int kt = ch * KC;
#pragma unroll
        for (int l = 0; l < 2; l++) {
            int grow = rowBase + ar + l * 64;
            aReg[l] = make_float4(0.f, 0.f, 0.f, 0.f);
            if (grow < Nn) aReg[l] = *(const float4*)&A[(size_t)grow * K + kt + ac];
        }
#pragma unroll
        for (int qi = 0; qi < 2; qi++)
#pragma unroll
            for (int j = 0; j < 4; j++)
                bReg[qi * 4 + j] = B[(size_t)(kt + (bq0 + qi) * 4 + j) * NC + colBase + bn];
    };

    auto store_smem = [&](int ch) {
        int kt = ch * KC;
#pragma unroll
        for (int l = 0; l < 2; l++) {
            float4 av = aReg[l];
            if (BNA) {
                av.x = av.x * s_sc[kt + ac + 0] + s_sh[kt + ac + 0];
                av.y = av.y * s_sc[kt + ac + 1] + s_sh[kt + ac + 1];
                av.z = av.z * s_sc[kt + ac + 2] + s_sh[kt + ac + 2];
                av.w = av.w * s_sc[kt + ac + 3] + s_sh[kt + ac + 3];
            }
            uint4 h4, l4;
            tf32_split(av.x, h4.x, l4.x);
            tf32_split(av.y, h4.y, l4.y);
            tf32_split(av.z, h4.z, l4.z);
            tf32_split(av.w, h4.w, l4.w);
            int off = (ar + l * 64) * AP + ac;
            *(uint4*)&Ah[off] = h4;
            *(uint4*)&Al[off] = l4;
        }
#pragma unroll
        for (int qi = 0; qi < 2; qi++) {
            uint4 h4, l4;
            tf32_split(bReg[qi * 4 + 0], h4.x, l4.x);
            tf32_split(bReg[qi * 4 + 1], h4.y, l4.y);
            tf32_split(bReg[qi * 4 + 2], h4.z, l4.z);
            tf32_split(bReg[qi * 4 + 3], h4.w, l4.w);
            int off = bn * BP + (bq0 + qi) * 4;
            *(uint4*)&Bh[off] = h4;
            *(uint4*)&Bl[off] = l4;
        }
    };

    load_regs(0);
    store_smem(0);
    __syncthreads();

    for (int ch = 0; ch < NCH; ch++) {
        bool hasNext = (ch + 1) < NCH;
        if (hasNext) load_regs(ch + 1);

#pragma unroll
        for (int kk = 0; kk < KC; kk += 8) {
            uint32_t ah[2][4], al[2][4];
#pragma unroll
            for (int fm = 0; fm < 2; fm++) {
                uint32_t d = (uint32_t)((fm * 16 * AP + kk) * 4);
                LDSM_X4(ah[fm][0], ah[fm][1], ah[fm][2], ah[fm][3], aOffH + d);
                LDSM_X4(al[fm][0], al[fm][1], al[fm][2], al[fm][3], aOffL + d);
            }
#pragma unroll
            for (int fnp = 0; fnp < 4; fnp++) {
                uint32_t bh[4], bl[4];
                uint32_t d = (uint32_t)((fnp * 16 * BP + kk) * 4);
                LDSM_X4(bh[0], bh[1], bh[2], bh[3], bOffH + d);
                LDSM_X4(bl[0], bl[1], bl[2], bl[3], bOffL + d);
#pragma unroll
                for (int fm = 0; fm < 2; fm++) {
                    mma8(acc[fm][2 * fnp], ah[fm], &bh[0]);
                    mma8(acc[fm][2 * fnp], ah[fm], &bl[0]);
                    mma8(acc[fm][2 * fnp], al[fm], &bh[0]);
                    mma8(acc[fm][2 * fnp + 1], ah[fm], &bh[2]);
                    mma8(acc[fm][2 * fnp + 1], ah[fm], &bl[2]);
                    mma8(acc[fm][2 * fnp + 1], al[fm], &bh[2]);
                }
            }
        }

        if (hasNext) {
            __syncthreads();
            store_smem(ch + 1);
            __syncthreads();
        }
    }

    // ---------------- epilogue ----------------
#pragma unroll
    for (int fm = 0; fm < 2; fm++) {
        int r0 = rowBase + wm * 32 + fm * 16 + lr;
        int r1 = r0 + 8;
        bool v0 = r0 < Nn, v1 = r1 < Nn;
#pragma unroll
        for (int fn = 0; fn < 8; fn++) {
            int cl = wn * 64 + fn * 8 + lc * 2;
            int gc = colBase + cl;
            float d0 = acc[fm][fn][0], d1 = acc[fm][fn][1];
            float d2 = acc[fm][fn][2], d3 = acc[fm][fn][3];
            if (BIAS) {
                float b0 = bias[gc], b1 = bias[gc + 1];
                d0 += b0; d1 += b1; d2 += b0; d3 += b1;
            }
            if (RES) {
                float sc0 = BNRES ? s_sc[cl] : 1.f, sh0 = BNRES ? s_sh[cl] : 0.f;
                float sc1 = BNRES ? s_sc[cl + 1] : 1.f, sh1 = BNRES ? s_sh[cl + 1] : 0.f;
                if (v0) {
                    float2 rv = *(const float2*)&res[(size_t)r0 * NC + gc];
                    d0 += rv.x * sc0 + sh0;
                    d1 += rv.y * sc1 + sh1;
                }
                if (v1) {
                    float2 rv = *(const float2*)&res[(size_t)r1 * NC + gc];
                    d2 += rv.x * sc0 + sh0;
                    d3 += rv.y * sc1 + sh1;
                }
            }
            if (RELU) {
                d0 = d0 > 0.f ? d0 : 0.f;
                d1 = d1 > 0.f ? d1 : 0.f;
                d2 = d2 > 0.f ? d2 : 0.f;
                d3 = d3 > 0.f ? d3 : 0.f;
            }
            if (STATS) {
                float e0 = v0 ? d0 : 0.f, e1 = v0 ? d1 : 0.f;
                float e2 = v1 ? d2 : 0.f, e3 = v1 ? d3 : 0.f;
                atomicAdd(&s_cs[cl], e0 + e2);
                atomicAdd(&s_cs[cl + 1], e1 + e3);
                atomicAdd(&s_cq[cl], e0 * e0 + e2 * e2);
                atomicAdd(&s_cq[cl + 1], e1 * e1 + e3 * e3);
            }
            if (v0) *(float2*)&C[(size_t)r0 * NC + gc] = make_float2(d0, d1);
            if (v1) *(float2*)&C[(size_t)r1 * NC + gc] = make_float2(d2, d3);
        }
    }

    if (STATS) {
        __syncthreads();
        if (tid < SSZ) {
            atomicAdd(&stsum[colBase + tid], (double)s_cs[tid]);
            atomicAdd(&stsq[colBase + tid], (double)s_cq[tid]);
        }
    }
}

// ---------------- fused edge attention: one warp per dst node ----------------
__global__ void attn_fused_kernel() {
    int warp = blockIdx.x * (blockDim.x >> 5) + (threadIdx.x >> 5);
    int lane = threadIdx.x & 31;
    if (warp >= Nn) return;
    int dst = warp;

    float4 q4 = *(const float4*)&g_q[dst * Dd + lane * 4];

    float m = -INFINITY;
    float l = 0.0f;
    float4 acc = make_float4(0.f, 0.f, 0.f, 0.f);

    int beg = g_rowptr[dst];
    int end = g_rowptr[dst + 1];
    for (int j = beg; j < end; j++) {
        int src = g_col[j];
        float4 k4 = *(const float4*)&g_k[src * Dd + lane * 4];
        float p = q4.x * k4.x + q4.y * k4.y + q4.z * k4.z + q4.w * k4.w;
        p += __shfl_xor_sync(0xffffffffu, p, 1);
        p += __shfl_xor_sync(0xffffffffu, p, 2);
        float s = p * 0.25f;

        float newm = fmaxf(m, s);
        float corr = __expf(m - newm);
        float pe = __expf(s - newm);
        float4 v4 = *(const float4*)&g_v[src * Dd + lane * 4];
        acc.x = acc.x * corr + pe * v4.x;
        acc.y = acc.y * corr + pe * v4.y;
        acc.z = acc.z * corr + pe * v4.z;
        acc.w = acc.w * corr + pe * v4.w;
        l = l * corr + pe;
        m = newm;
    }
    float inv = (l > 0.f) ? (1.0f / l) : 0.0f;
    acc.x *= inv; acc.y *= inv; acc.z *= inv; acc.w *= inv;
    *(float4*)&g_attn[dst * Dd + lane * 4] = acc;
}

// ---------------- final projection (with fused BN on input) ----------------
__global__ void proj_kernel(const float* __restrict__ Wp, const float* __restrict__ bp,
                            const float* __restrict__ bng, const float* __restrict__ bnb,
                            float* __restrict__ out) {
    int warp = blockIdx.x * (blockDim.x >> 5) + (threadIdx.x >> 5);
    int lane = threadIdx.x & 31;
    if (warp >= Nn) return;

    float sc[4], sh[4];
#pragma unroll
    for (int i = 0; i < 4; i++) {
        int c = lane + 32 * i;
        double m = g_sum2[c] / (double)Nn;
        double var = g_sq2[c] / (double)Nn - m * m;
        float s = rsqrtf((float)var + EPSf) * bng[c];
        sc[i] = s;
        sh[i] = bnb[c] - (float)m * s;
    }

    float acc[Cc] = {0.f, 0.f, 0.f, 0.f, 0.f};
#pragma unroll
    for (int i = 0; i < 4; i++) {
        int k = lane + 32 * i;
        float xv = g_tmp2[warp * Dd + k] * sc[i] + sh[i];
#pragma unroll
        for (int c = 0; c < Cc; c++) acc[c] += xv * Wp[k * Cc + c];
    }
#pragma unroll
    for (int c = 0; c < Cc; c++) {
#pragma unroll
        for (int o = 16; o > 0; o >>= 1) acc[c] += __shfl_down_sync(0xffffffffu, acc[c], o);
    }
    if (lane == 0) {
#pragma unroll
        for (int c = 0; c < Cc; c++) out[warp * Cc + c] = acc[c] + bp[c];
    }
}

// ---------------- launch ----------------
extern "C" void kernel_launch(void* const* d_in, const int* in_sizes, int n_in,
                              void* d_out, int out_size) {
    const float* x   = (const float*)d_in[0];
    const int*   ei  = (const int*)d_in[1];
    const float* Wq  = (const float*)d_in[2];
    const float* Wk  = (const float*)d_in[3];
    const float* Wv  = (const float*)d_in[4];
    const float* Wo  = (const float*)d_in[5];
    const float* g1  = (const float*)d_in[6];
    const float* bn1 = (const float*)d_in[7];
    const float* W1  = (const float*)d_in[8];
    const float* bf1 = (const float*)d_in[9];
    const float* W2  = (const float*)d_in[10];
    const float* bf2 = (const float*)d_in[11];
    const float* g2  = (const float*)d_in[12];
    const float* bn2 = (const float*)d_in[13];
    const float* Wp  = (const float*)d_in[14];
    const float* bp  = (const float*)d_in[15];
    float* out = (float*)d_out;

    float *pq, *pk, *pv, *pattn, *ptmp1, *ptmp2, *pff;
    double *psum1, *psq1, *psum2, *psq2;
    cudaGetSymbolAddress((void**)&pq, g_q);
    cudaGetSymbolAddress((void**)&pk, g_k);
    cudaGetSymbolAddress((void**)&pv, g_v);
    cudaGetSymbolAddress((void**)&pattn, g_attn);
    cudaGetSymbolAddress((void**)&ptmp1, g_tmp1);
    cudaGetSymbolAddress((void**)&ptmp2, g_tmp2);
    cudaGetSymbolAddress((void**)&pff, g_ff);
    cudaGetSymbolAddress((void**)&psum1, g_sum1);
    cudaGetSymbolAddress((void**)&psq1, g_sq1);
    cudaGetSymbolAddress((void**)&psum2, g_sum2);
    cudaGetSymbolAddress((void**)&psq2, g_sq2);

    const int gemmRows = (Nn + 127) / 128;  // 391
    const int edgeBlocks = (Ee + 255) / 256;
    const int nodeBlocks = (Nn + 255) / 256;
    const int warpBlocks = (Nn + 7) / 8;

    csr_zero_kernel<<<nodeBlocks, 256>>>();
    csr_hist_kernel<<<edgeBlocks, 256>>>(ei);
    csr_scan1_kernel<<<SCAN_NB, SCAN_B>>>();
    // #4: layer-0 QKV (profiled launch)
    wm_gemm_kernel<Dd, Dd, false, false, false, false, false, false, 3>
        <<<dim3(gemmRows, 3), 256>>>(x, Wq, Wk, Wv, nullptr, nullptr,
                                     nullptr, nullptr, nullptr, nullptr,
                                     nullptr, nullptr, pq, pk, pv);
    csr_scan23_kernel<<<SCAN_NB, SCAN_B>>>();
    csr_scatter_kernel<<<edgeBlocks, 256>>>(ei);

    for (int i = 0; i < Ll; i++) {
        const float* wq = Wq + (size_t)i * Dd * Dd;
        const float* wk = Wk + (size_t)i * Dd * Dd;
        const float* wv = Wv + (size_t)i * Dd * Dd;
        const float* wo = Wo + (size_t)i * Dd * Dd;
        const float* w1 = W1 + (size_t)i * Dd * FFd;
        const float* w2 = W2 + (size_t)i * FFd * Dd;

        if (i > 0) {
            wm_gemm_kernel<Dd, Dd, false, false, false, true, false, false, 3>
                <<<dim3(gemmRows, 3), 256>>>(
                    ptmp2, wq, wk, wv, nullptr, nullptr,
                    g2 + (i - 1) * Dd, bn2 + (i - 1) * Dd,
                    psum2, psq2, nullptr, nullptr, pq, pk, pv);
        }

        attn_fused_kernel<<<warpBlocks, 256>>>();

        zero_stats_kernel<<<1, 128>>>(psum1, psq1);

        if (i == 0) {
            wm_gemm_kernel<Dd, Dd, false, false, true, false, false, true, 1>
                <<<dim3(gemmRows, 1), 256>>>(
                    pattn, wo, nullptr, nullptr, nullptr, x,
                    nullptr, nullptr, nullptr, nullptr,
                    psum1, psq1, ptmp1, nullptr, nullptr);
        } else {
            wm_gemm_kernel<Dd, Dd, false, false, true, false, true, true, 1>
                <<<dim3(gemmRows, 1), 256>>>(
                    pattn, wo, nullptr, nullptr, nullptr, ptmp2,
                    g2 + (i - 1) * Dd, bn2 + (i - 1) * Dd,
                    psum2, psq2, psum1, psq1, ptmp1, nullptr, nullptr);
        }

        wm_gemm_kernel<Dd, FFd, true, true, false, true, false, false, 1>
            <<<dim3(gemmRows, 2), 256>>>(
                ptmp1, w1, nullptr, nullptr, bf1 + i * FFd, nullptr,
                g1 + i * Dd, bn1 + i * Dd,
                psum1, psq1, nullptr, nullptr, pff, nullptr, nullptr);

        zero_stats_kernel<<<1, 128>>>(psum2, psq2);

        wm_gemm_kernel<FFd, Dd, true, false, true, false, true, true, 1>
            <<<dim3(gemmRows, 1), 256>>>(
                pff, w2, nullptr, nullptr, bf2 + i * Dd, ptmp1,
                g1 + i * Dd, bn1 + i * Dd,
                psum1, psq1, psum2, psq2, ptmp2, nullptr, nullptr);
    }

    proj_kernel<<<warpBlocks, 256>>>(Wp, bp, g2 + (Ll - 1) * Dd, bn2 + (Ll - 1) * Dd, out);
}

// round 10
// speedup vs baseline: 1.2399x; 1.2399x over previous
#include <cuda_runtime.h>
#include <math.h>
#include <stdint.h>

#define Nn 50000
#define Ee 640000
#define Dd 128
#define Hh 8
#define DHd 16
#define FFd 256
#define Cc 5
#define Ll 6
#define EPSf 1e-5f

#define SCAN_B 1024
#define SCAN_NB ((Nn + SCAN_B - 1) / SCAN_B)  // 49

// split-weight storage offsets (floats)
#define OFF_WQ 0
#define OFF_WK 98304
#define OFF_WV 196608
#define OFF_WO 294912
#define OFF_W1 393216
#define OFF_W2 589824
#define WSPLIT_TOTAL 786432

// ---------------- scratch (device globals; no allocs allowed) ----------------
__device__ float g_q[Nn * Dd];
__device__ float g_k[Nn * Dd];
__device__ float g_v[Nn * Dd];
__device__ float g_attn[Nn * Dd];
__device__ float g_tmp1[Nn * Dd];
__device__ float g_tmp2[Nn * Dd];
__device__ float g_ff[Nn * FFd];
__device__ float g_wh[WSPLIT_TOTAL];
__device__ float g_wl[WSPLIT_TOTAL];
__device__ double g_sum1[Dd];
__device__ double g_sq1[Dd];
__device__ double g_sum2[Dd];
__device__ double g_sq2[Dd];
// CSR
__device__ int g_deg[Nn];
__device__ int g_cursor[Nn];
__device__ int g_rowptr[Nn + 1];
__device__ int g_scan[Nn];
__device__ int g_bsum[SCAN_NB];
__device__ int g_col[Ee];

// ---------------- tf32 / mma / cp.async helpers (baseline PTX only) ---------
__device__ __forceinline__ void tf32_split(float x, uint32_t& hi, uint32_t& lo) {
    uint32_t h;
    asm("cvt.rna.tf32.f32 %0, %1;" : "=r"(h) : "f"(x));
    float l = x - __uint_as_float(h);
    uint32_t lw;
    asm("cvt.rna.tf32.f32 %0, %1;" : "=r"(lw) : "f"(l));
    hi = h;
    lo = lw;
}

__device__ __forceinline__ void mma8(float* c, const uint32_t* a, const uint32_t* b) {
    asm volatile(
        "mma.sync.aligned.m16n8k8.row.col.f32.tf32.tf32.f32 "
        "{%0,%1,%2,%3}, {%4,%5,%6,%7}, {%8,%9}, {%0,%1,%2,%3};"
        : "+f"(c[0]), "+f"(c[1]), "+f"(c[2]), "+f"(c[3])
        : "r"(a[0]), "r"(a[1]), "r"(a[2]), "r"(a[3]), "r"(b[0]), "r"(b[1]));
}

#define LDSM_X4(R0, R1, R2, R3, ADDR)                                        \
    asm volatile("ldmatrix.sync.aligned.m8n8.x4.shared.b16 {%0,%1,%2,%3}, [%4];" \
                 : "=r"(R0), "=r"(R1), "=r"(R2), "=r"(R3) : "r"(ADDR))

__device__ __forceinline__ void cp_async16(uint32_t dst, const void* src, int szbytes) {
    asm volatile("cp.async.cg.shared.global [%0], [%1], 16, %2;"
                 :: "r"(dst), "l"(src), "r"(szbytes));
}
#define CP_COMMIT() asm volatile("cp.async.commit_group;" ::: "memory")
#define CP_WAIT0() asm volatile("cp.async.wait_group 0;" ::: "memory")

// ---------------- weight pre-split kernels ----------------
// out[m][n][k] (k contiguous) = split(W[m][k][n]) for nmat matrices of KxNC
__global__ void split_weights_kernel(const float* __restrict__ W,
                                     float* __restrict__ wh, float* __restrict__ wl,
                                     int K, int NC, int total) {
    int idx = blockIdx.x * 256 + threadIdx.x;
    if (idx >= total) return;
    int per = K * NC;
    int m = idx / per;
    int r = idx - m * per;
    int n = r / K;
    int k = r - n * K;
    float v = W[(size_t)m * per + (size_t)k * NC + n];
    uint32_t hi, lo;
    tf32_split(v, hi, lo);
    wh[idx] = __uint_as_float(hi);
    wl[idx] = __uint_as_float(lo);
}

// QKVO combined: 4 families of Ll 128x128 matrices
__global__ void split_qkvo_kernel(const float* __restrict__ Wq, const float* __restrict__ Wk,
                                  const float* __restrict__ Wv, const float* __restrict__ Wo,
                                  float* __restrict__ wh, float* __restrict__ wl) {
    int idx = blockIdx.x * 256 + threadIdx.x;
    const int famSz = Ll * Dd * Dd;  // 98304
    if (idx >= 4 * famSz) return;
    int fam = idx / famSz;
    int r = idx - fam * famSz;
    int m = r / (Dd * Dd);
    int e = r - m * Dd * Dd;
    int n = e / Dd;
    int k = e - n * Dd;
    const float* W = fam == 0 ? Wq : (fam == 1 ? Wk : (fam == 2 ? Wv : Wo));
    float v = W[(size_t)m * Dd * Dd + (size_t)k * Dd + n];
    uint32_t hi, lo;
    tf32_split(v, hi, lo);
    wh[idx] = __uint_as_float(hi);
    wl[idx] = __uint_as_float(lo);
}

// ---------------- CSR build ----------------
__global__ void csr_zero_kernel() {
    int i = blockIdx.x * blockDim.x + threadIdx.x;
    if (i < Nn) {
        g_deg[i] = 0;
        g_cursor[i] = 0;
    }
}

__global__ void csr_hist_kernel(const int* __restrict__ ei) {
    int e = blockIdx.x * blockDim.x + threadIdx.x;
    if (e < Ee) atomicAdd(&g_deg[ei[Ee + e]], 1);
}

__global__ void csr_scan1_kernel() {
    __shared__ int sh[SCAN_B];
    int gi = blockIdx.x * SCAN_B + threadIdx.x;
    int v = (gi < Nn) ? g_deg[gi] : 0;
    sh[threadIdx.x] = v;
    __syncthreads();
#pragma unroll
    for (int off = 1; off < SCAN_B; off <<= 1) {
        int t = (threadIdx.x >= off) ? sh[threadIdx.x - off] : 0;
        __syncthreads();
        sh[threadIdx.x] += t;
        __syncthreads();
    }
    if (gi < Nn) g_scan[gi] = sh[threadIdx.x];
    if (threadIdx.x == SCAN_B - 1) g_bsum[blockIdx.x] = sh[threadIdx.x];
}

__global__ void csr_scan23_kernel() {
    __shared__ int soff;
    if (threadIdx.x == 0) {
        int acc = 0;
        for (int i = 0; i < (int)blockIdx.x; i++) acc += g_bsum[i];
        soff = acc;
    }
    __syncthreads();
    int gi = blockIdx.x * SCAN_B + threadIdx.x;
    if (gi < Nn) g_rowptr[gi + 1] = g_scan[gi] + soff;
    if (gi == 0) g_rowptr[0] = 0;
}

__global__ void csr_scatter_kernel(const int* __restrict__ ei) {
    int e = blockIdx.x * blockDim.x + threadIdx.x;
    if (e >= Ee) return;
    int src = ei[e], dst = ei[Ee + e];
    int pos = g_rowptr[dst] + atomicAdd(&g_cursor[dst], 1);
    g_col[pos] = src;
}

__global__ void zero_stats_kernel(double* __restrict__ a, double* __restrict__ b) {
    int t = threadIdx.x;
    if (t < Dd) {
        a[t] = 0.0;
        b[t] = 0.0;
    }
}

// ---------------- warp-mma tf32 GEMM: cp.async double-buffered ----------------
// C[M,NC] = op(A)[M,K] @ W[K,NC] (+bias)(+op(res))(relu)
// Weights pre-split (hi/lo, [n][k]) in wh/wl at off*. A raw fp32 in smem,
// split in registers after ldmatrix. CTA tile 128x128, 8 warps, KC=16.
template <int K, int NC, bool BIAS, bool RELU, bool RES, bool BNA, bool BNRES,
          bool STATS, int NMAT>
__global__ __launch_bounds__(256, 2) void wm_gemm_kernel(
    const float* __restrict__ A,
    const float* __restrict__ wh, const float* __restrict__ wl,
    int off0, int off1, int off2,
    const float* __restrict__ bias, const float* __restrict__ res,
    const float* __restrict__ bng, const float* __restrict__ bnb,
    const double* __restrict__ bnsum, const double* __restrict__ bnsq,
    double* __restrict__ stsum, double* __restrict__ stsq,
    float* __restrict__ C0, float* __restrict__ C1, float* __restrict__ C2) {
    const int KC = 16;
    const int NCH = K / KC;
    const int YPM = NC / 128;
    constexpr int PSZ = BNA ? K : (BNRES ? 128 : 1);
    constexpr int SSZ = STATS ? 128 : 1;
    const int AP = 20;
    const int BP = 20;

    __shared__ float As[2][128 * AP];
    __shared__ uint32_t Bhs[2][128 * BP], Bls[2][128 * BP];
    __shared__ float s_sc[PSZ], s_sh[PSZ];
    __shared__ float s_cs[SSZ], s_cq[SSZ];

    int tid = threadIdx.x;
    int lane = tid & 31;
    int wid = tid >> 5;
    int wm = wid >> 1;
    int wn = wid & 1;
    int lr = lane >> 2;
    int lc = lane & 3;
    int rowBase = blockIdx.x * 128;
    int mat = (NMAT > 1) ? ((int)blockIdx.y / YPM) : 0;
    int colBase = ((int)blockIdx.y % YPM) * 128;
    size_t boff = (size_t)((NMAT > 1) ? (mat == 0 ? off0 : (mat == 1 ? off1 : off2)) : off0);
    float* C = (NMAT > 1) ? (mat == 0 ? C0 : (mat == 1 ? C1 : C2)) : C0;

    if (BNA || BNRES) {
        for (int c = tid; c < PSZ; c += 256) {
            double m = bnsum[c] / (double)Nn;
            double var = bnsq[c] / (double)Nn - m * m;
            float sc = rsqrtf((float)var + EPSf) * bng[c];
            s_sc[c] = sc;
            s_sh[c] = bnb[c] - (float)m * sc;
        }
    }
    if (STATS) {
        if (tid < SSZ) {
            s_cs[tid] = 0.f;
            s_cq[tid] = 0.f;
        }
    }

    float acc[2][8][4];
#pragma unroll
    for (int i = 0; i < 2; i++)
#pragma unroll
        for (int j = 0; j < 8; j++)
#pragma unroll
            for (int t = 0; t < 4; t++) acc[i][j][t] = 0.f;

    // smem base addresses
    uint32_t asB[2], bhB[2], blB[2];
    asB[0] = (uint32_t)__cvta_generic_to_shared(&As[0][0]);
    asB[1] = (uint32_t)__cvta_generic_to_shared(&As[1][0]);
    bhB[0] = (uint32_t)__cvta_generic_to_shared(&Bhs[0][0]);
    bhB[1] = (uint32_t)__cvta_generic_to_shared(&Bhs[1][0]);
    blB[0] = (uint32_t)__cvta_generic_to_shared(&Bls[0][0]);
    blB[1] = (uint32_t)__cvta_generic_to_shared(&Bls[1][0]);

    // ldmatrix per-lane offsets (validated mapping from R9)
    const int aRow = (lane & 7) + ((lane >> 3) & 1) * 8;
    const int aK = ((lane >> 4) & 1) * 4;
    const int bRow = (lane & 7) + ((lane >> 4) & 1) * 8;
    const int bK = ((lane >> 3) & 1) * 4;
    const uint32_t aLane = (uint32_t)(((wm * 32 + aRow) * AP + aK) * 4);
    const uint32_t bLane = (uint32_t)(((wn * 64 + bRow) * BP + bK) * 4);

    auto fill = [&](int ch, int buf) {
        int kt = ch * KC;
#pragma unroll
        for (int l = 0; l < 2; l++) {
            int u = tid + 256 * l;
            int m_ = u >> 2;
            int kq = u & 3;
            int grow = rowBase + m_;
            bool valid = grow < Nn;
            const float* src = &A[(size_t)(valid ? grow : 0) * K + kt + kq * 4];
            cp_async16(asB[buf] + (uint32_t)((m_ * AP + kq * 4) * 4), src, valid ? 16 : 0);
        }
#pragma unroll
        for (int l = 0; l < 2; l++) {
            int u = tid + 256 * l;
            int n_ = u >> 2;
            int kq = u & 3;
            size_t goff = boff + (size_t)(colBase + n_) * K + kt + kq * 4;
            uint32_t doff = (uint32_t)((n_ * BP + kq * 4) * 4);
            cp_async16(bhB[buf] + doff, wh + goff, 16);
            cp_async16(blB[buf] + doff, wl + goff, 16);
        }
        CP_COMMIT();
    };

    fill(0, 0);
    CP_WAIT0();
    __syncthreads();
    int buf = 0;

    for (int ch = 0; ch < NCH; ch++) {
        bool hasNext = (ch + 1) < NCH;
        if (hasNext) fill(ch + 1, buf ^ 1);

        uint32_t aBase = asB[buf] + aLane;
        uint32_t bhBase = bhB[buf] + bLane;
        uint32_t blBase = blB[buf] + bLane;

#pragma unroll
        for (int kk = 0; kk < KC; kk += 8) {
            // A raw fragments
            uint32_t ar_[2][4];
#pragma unroll
            for (int fm = 0; fm < 2; fm++) {
                uint32_t d = (uint32_t)((fm * 16 * AP + kk) * 4);
                LDSM_X4(ar_[fm][0], ar_[fm][1], ar_[fm][2], ar_[fm][3], aBase + d);
            }
            // split (+BN) in registers
            float sc0 = 1.f, sh0 = 0.f, sc4 = 1.f, sh4 = 0.f;
            if (BNA) {
                int kb = ch * KC + kk + lc;
                sc0 = s_sc[kb];
                sh0 = s_sh[kb];
                sc4 = s_sc[kb + 4];
                sh4 = s_sh[kb + 4];
            }
            uint32_t ah[2][4], al[2][4];
#pragma unroll
            for (int fm = 0; fm < 2; fm++)
#pragma unroll
                for (int j = 0; j < 4; j++) {
                    float v = __uint_as_float(ar_[fm][j]);
                    if (BNA) v = v * (j < 2 ? sc0 : sc4) + (j < 2 ? sh0 : sh4);
                    tf32_split(v, ah[fm][j], al[fm][j]);
                }
#pragma unroll
            for (int fnp = 0; fnp < 4; fnp++) {
                uint32_t bh[4], bl[4];
                uint32_t d = (uint32_t)((fnp * 16 * BP + kk) * 4);
                LDSM_X4(bh[0], bh[1], bh[2], bh[3], bhBase + d);
                LDSM_X4(bl[0], bl[1], bl[2], bl[3], blBase + d);
#pragma unroll
                for (int fm = 0; fm < 2; fm++) {
                    mma8(acc[fm][2 * fnp], ah[fm], &bh[0]);
                    mma8(acc[fm][2 * fnp], ah[fm], &bl[0]);
                    mma8(acc[fm][2 * fnp], al[fm], &bh[0]);
                    mma8(acc[fm][2 * fnp + 1], ah[fm], &bh[2]);
                    mma8(acc[fm][2 * fnp + 1], ah[fm], &bl[2]);
                    mma8(acc[fm][2 * fnp + 1], al[fm], &bh[2]);
                }
            }
        }

        if (hasNext) {
            CP_WAIT0();
            __syncthreads();
            buf ^= 1;
        }
    }

    // ---------------- epilogue ----------------
#pragma unroll
    for (int fm = 0; fm < 2; fm++) {
        int r0 = rowBase + wm * 32 + fm * 16 + lr;
        int r1 = r0 + 8;
        bool v0 = r0 < Nn, v1 = r1 < Nn;
#pragma unroll
        for (int fn = 0; fn < 8; fn++) {
            int cl = wn * 64 + fn * 8 + lc * 2;
            int gc = colBase + cl;
            float d0 = acc[fm][fn][0], d1 = acc[fm][fn][1];
            float d2 = acc[fm][fn][2], d3 = acc[fm][fn][3];
            if (BIAS) {
                float b0 = bias[gc], b1 = bias[gc + 1];
                d0 += b0; d1 += b1; d2 += b0; d3 += b1;
            }
            if (RES) {
                float sc0 = BNRES ? s_sc[cl] : 1.f, sh0 = BNRES ? s_sh[cl] : 0.f;
                float sc1 = BNRES ? s_sc[cl + 1] : 1.f, sh1 = BNRES ? s_sh[cl + 1] : 0.f;
                if (v0) {
                    float2 rv = *(const float2*)&res[(size_t)r0 * NC + gc];
                    d0 += rv.x * sc0 + sh0;
                    d1 += rv.y * sc1 + sh1;
                }
                if (v1) {
                    float2 rv = *(const float2*)&res[(size_t)r1 * NC + gc];
                    d2 += rv.x * sc0 + sh0;
                    d3 += rv.y * sc1 + sh1;
                }
            }
            if (RELU) {
                d0 = d0 > 0.f ? d0 : 0.f;
                d1 = d1 > 0.f ? d1 : 0.f;
                d2 = d2 > 0.f ? d2 : 0.f;
                d3 = d3 > 0.f ? d3 : 0.f;
            }
            if (STATS) {
                float e0 = v0 ? d0 : 0.f, e1 = v0 ? d1 : 0.f;
                float e2 = v1 ? d2 : 0.f, e3 = v1 ? d3 : 0.f;
                atomicAdd(&s_cs[cl], e0 + e2);
                atomicAdd(&s_cs[cl + 1], e1 + e3);
                atomicAdd(&s_cq[cl], e0 * e0 + e2 * e2);
                atomicAdd(&s_cq[cl + 1], e1 * e1 + e3 * e3);
            }
            if (v0) *(float2*)&C[(size_t)r0 * NC + gc] = make_float2(d0, d1);
            if (v1) *(float2*)&C[(size_t)r1 * NC + gc] = make_float2(d2, d3);
        }
    }

    if (STATS) {
        __syncthreads();
        if (tid < SSZ) {
            atomicAdd(&stsum[colBase + tid], (double)s_cs[tid]);
            atomicAdd(&stsq[colBase + tid], (double)s_cq[tid]);
        }
    }
}

// ---------------- fused edge attention: one warp per dst node ----------------
__global__ void attn_fused_kernel() {
    int warp = blockIdx.x * (blockDim.x >> 5) + (threadIdx.x >> 5);
    int lane = threadIdx.x & 31;
    if (warp >= Nn) return;
    int dst = warp;

    float4 q4 = *(const float4*)&g_q[dst * Dd + lane * 4];

    float m = -INFINITY;
    float l = 0.0f;
    float4 acc = make_float4(0.f, 0.f, 0.f, 0.f);

    int beg = g_rowptr[dst];
    int end = g_rowptr[dst + 1];
    for (int j = beg; j < end; j++) {
        int src = g_col[j];
        float4 k4 = *(const float4*)&g_k[src * Dd + lane * 4];
        float p = q4.x * k4.x + q4.y * k4.y + q4.z * k4.z + q4.w * k4.w;
        p += __shfl_xor_sync(0xffffffffu, p, 1);
        p += __shfl_xor_sync(0xffffffffu, p, 2);
        float s = p * 0.25f;

        float newm = fmaxf(m, s);
        float corr = __expf(m - newm);
        float pe = __expf(s - newm);
        float4 v4 = *(const float4*)&g_v[src * Dd + lane * 4];
        acc.x = acc.x * corr + pe * v4.x;
        acc.y = acc.y * corr + pe * v4.y;
        acc.z = acc.z * corr + pe * v4.z;
        acc.w = acc.w * corr + pe * v4.w;
        l = l * corr + pe;
        m = newm;
    }
    float inv = (l > 0.f) ? (1.0f / l) : 0.0f;
    acc.x *= inv; acc.y *= inv; acc.z *= inv; acc.w *= inv;
    *(float4*)&g_attn[dst * Dd + lane * 4] = acc;
}

// ---------------- final projection (with fused BN on input) ----------------
__global__ void proj_kernel(const float* __restrict__ Wp, const float* __restrict__ bp,
                            const float* __restrict__ bng, const float* __restrict__ bnb,
                            float* __restrict__ out) {
    int warp = blockIdx.x * (blockDim.x >> 5) + (threadIdx.x >> 5);
    int lane = threadIdx.x & 31;
    if (warp >= Nn) return;

    float sc[4], sh[4];
#pragma unroll
    for (int i = 0; i < 4; i++) {
        int c = lane + 32 * i;
        double m = g_sum2[c] / (double)Nn;
        double var = g_sq2[c] / (double)Nn - m * m;
        float s = rsqrtf((float)var + EPSf) * bng[c];
        sc[i] = s;
        sh[i] = bnb[c] - (float)m * s;
    }

    float acc[Cc] = {0.f, 0.f, 0.f, 0.f, 0.f};
#pragma unroll
    for (int i = 0; i < 4; i++) {
        int k = lane + 32 * i;
        float xv = g_tmp2[warp * Dd + k] * sc[i] + sh[i];
#pragma unroll
        for (int c = 0; c < Cc; c++) acc[c] += xv * Wp[k * Cc + c];
    }
#pragma unroll
    for (int c = 0; c < Cc; c++) {
#pragma unroll
        for (int o = 16; o > 0; o >>= 1) acc[c] += __shfl_down_sync(0xffffffffu, acc[c], o);
    }
    if (lane == 0) {
#pragma unroll
        for (int c = 0; c < Cc; c++) out[warp * Cc + c] = acc[c] + bp[c];
    }
}

// ---------------- launch ----------------
extern "C" void kernel_launch(void* const* d_in, const int* in_sizes, int n_in,
                              void* d_out, int out_size) {
    const float* x   = (const float*)d_in[0];
    const int*   ei  = (const int*)d_in[1];
    const float* Wq  = (const float*)d_in[2];
    const float* Wk  = (const float*)d_in[3];
    const float* Wv  = (const float*)d_in[4];
    const float* Wo  = (const float*)d_in[5];
    const float* g1  = (const float*)d_in[6];
    const float* bn1 = (const float*)d_in[7];
    const float* W1  = (const float*)d_in[8];
    const float* bf1 = (const float*)d_in[9];
    const float* W2  = (const float*)d_in[10];
    const float* bf2 = (const float*)d_in[11];
    const float* g2  = (const float*)d_in[12];
    const float* bn2 = (const float*)d_in[13];
    const float* Wp  = (const float*)d_in[14];
    const float* bp  = (const float*)d_in[15];
    float* out = (float*)d_out;

    float *pq, *pk, *pv, *pattn, *ptmp1, *ptmp2, *pff, *pwh, *pwl;
    double *psum1, *psq1, *psum2, *psq2;
    cudaGetSymbolAddress((void**)&pq, g_q);
    cudaGetSymbolAddress((void**)&pk, g_k);
    cudaGetSymbolAddress((void**)&pv, g_v);
    cudaGetSymbolAddress((void**)&pattn, g_attn);
    cudaGetSymbolAddress((void**)&ptmp1, g_tmp1);
    cudaGetSymbolAddress((void**)&ptmp2, g_tmp2);
    cudaGetSymbolAddress((void**)&pff, g_ff);
    cudaGetSymbolAddress((void**)&pwh, g_wh);
    cudaGetSymbolAddress((void**)&pwl, g_wl);
    cudaGetSymbolAddress((void**)&psum1, g_sum1);
    cudaGetSymbolAddress((void**)&psq1, g_sq1);
    cudaGetSymbolAddress((void**)&psum2, g_sum2);
    cudaGetSymbolAddress((void**)&psq2, g_sq2);

    const int gemmRows = (Nn + 127) / 128;  // 391
    const int edgeBlocks = (Ee + 255) / 256;
    const int nodeBlocks = (Nn + 255) / 256;
    const int warpBlocks = (Nn + 7) / 8;

    // #1..#3
    csr_zero_kernel<<<nodeBlocks, 256>>>();
    csr_hist_kernel<<<edgeBlocks, 256>>>(ei);
    split_qkvo_kernel<<<(4 * Ll * Dd * Dd + 255) / 256, 256>>>(Wq, Wk, Wv, Wo,
                                                               pwh, pwl);
    // #4: layer-0 QKV (profiled launch)
    wm_gemm_kernel<Dd, Dd, false, false, false, false, false, false, 3>
        <<<dim3(gemmRows, 3), 256>>>(x, pwh, pwl,
                                     OFF_WQ, OFF_WK, OFF_WV,
                                     nullptr, nullptr, nullptr, nullptr,
                                     nullptr, nullptr, nullptr, nullptr,
                                     pq, pk, pv);
    // #5..#8: remaining weight splits + CSR
    split_weights_kernel<<<(Ll * Dd * FFd + 255) / 256, 256>>>(
        W1, pwh + OFF_W1, pwl + OFF_W1, Dd, FFd, Ll * Dd * FFd);
    split_weights_kernel<<<(Ll * FFd * Dd + 255) / 256, 256>>>(
        W2, pwh + OFF_W2, pwl + OFF_W2, FFd, Dd, Ll * FFd * Dd);
    csr_scan1_kernel<<<SCAN_NB, SCAN_B>>>();
    csr_scan23_kernel<<<SCAN_NB, SCAN_B>>>();
    csr_scatter_kernel<<<edgeBlocks, 256>>>(ei);

    for (int i = 0; i < Ll; i++) {
        if (i > 0) {
            wm_gemm_kernel<Dd, Dd, false, false, false, true, false, false, 3>
                <<<dim3(gemmRows, 3), 256>>>(
                    ptmp2, pwh, pwl,
                    OFF_WQ + i * 16384, OFF_WK + i * 16384, OFF_WV + i * 16384,
                    nullptr, nullptr,
                    g2 + (i - 1) * Dd, bn2 + (i - 1) * Dd,
                    psum2, psq2, nullptr, nullptr, pq, pk, pv);
        }

        attn_fused_kernel<<<warpBlocks, 256>>>();

        zero_stats_kernel<<<1, 128>>>(psum1, psq1);

        if (i == 0) {
            wm_gemm_kernel<Dd, Dd, false, false, true, false, false, true, 1>
                <<<dim3(gemmRows, 1), 256>>>(
                    pattn, pwh, pwl, OFF_WO, 0, 0,
                    nullptr, x, nullptr, nullptr, nullptr, nullptr,
                    psum1, psq1, ptmp1, nullptr, nullptr);
        } else {
            wm_gemm_kernel<Dd, Dd, false, false, true, false, true, true, 1>
                <<<dim3(gemmRows, 1), 256>>>(
                    pattn, pwh, pwl, OFF_WO + i * 16384, 0, 0,
                    nullptr, ptmp2,
                    g2 + (i - 1) * Dd, bn2 + (i - 1) * Dd,
                    psum2, psq2, psum1, psq1, ptmp1, nullptr, nullptr);
        }

        wm_gemm_kernel<Dd, FFd, true, true, false, true, false, false, 1>
            <<<dim3(gemmRows, 2), 256>>>(
                ptmp1, pwh, pwl, OFF_W1 + i * 32768, 0, 0,
                bf1 + i * FFd, nullptr,
                g1 + i * Dd, bn1 + i * Dd,
                psum1, psq1, nullptr, nullptr, pff, nullptr, nullptr);

        zero_stats_kernel<<<1, 128>>>(psum2, psq2);

        wm_gemm_kernel<FFd, Dd, true, false, true, false, true, true, 1>
            <<<dim3(gemmRows, 1), 256>>>(
                pff, pwh, pwl, OFF_W2 + i * 32768, 0, 0,
                bf2 + i * Dd, ptmp1,
                g1 + i * Dd, bn1 + i * Dd,
                psum1, psq1, psum2, psq2, ptmp2, nullptr, nullptr);
    }

    proj_kernel<<<warpBlocks, 256>>>(Wp, bp, g2 + (Ll - 1) * Dd, bn2 + (Ll - 1) * Dd, out);
}

// round 11
// speedup vs baseline: 1.2666x; 1.0215x over previous
#include <cuda_runtime.h>
#include <math.h>
#include <stdint.h>

#define Nn 50000
#define Ee 640000
#define Dd 128
#define Hh 8
#define DHd 16
#define FFd 256
#define Cc 5
#define Ll 6
#define EPSf 1e-5f

#define SCAN_B 1024
#define SCAN_NB ((Nn + SCAN_B - 1) / SCAN_B)  // 49

// split-weight storage offsets (floats)
#define OFF_WQ 0
#define OFF_WK 98304
#define OFF_WV 196608
#define OFF_WO 294912
#define OFF_W1 393216
#define OFF_W2 589824
#define WSPLIT_TOTAL 786432

// ---------------- scratch (device globals; no allocs allowed) ----------------
__device__ float g_q[Nn * Dd];
__device__ float g_k[Nn * Dd];
__device__ float g_v[Nn * Dd];
__device__ float g_attn[Nn * Dd];
__device__ float g_tmp1[Nn * Dd];
__device__ float g_tmp2[Nn * Dd];
__device__ float g_ff[Nn * FFd];
__device__ float g_wh[WSPLIT_TOTAL];
__device__ float g_wl[WSPLIT_TOTAL];
__device__ double g_sum1[Dd];
__device__ double g_sq1[Dd];
__device__ double g_sum2[Dd];
__device__ double g_sq2[Dd];
// CSR
__device__ int g_deg[Nn];
__device__ int g_cursor[Nn];
__device__ int g_rowptr[Nn + 1];
__device__ int g_scan[Nn];
__device__ int g_bsum[SCAN_NB];
__device__ int g_col[Ee];

// ---------------- tf32 / mma / cp.async helpers (baseline PTX only) ---------
__device__ __forceinline__ void tf32_split(float x, uint32_t& hi, uint32_t& lo) {
    uint32_t h;
    asm("cvt.rna.tf32.f32 %0, %1;" : "=r"(h) : "f"(x));
    float l = x - __uint_as_float(h);
    uint32_t lw;
    asm("cvt.rna.tf32.f32 %0, %1;" : "=r"(lw) : "f"(l));
    hi = h;
    lo = lw;
}

__device__ __forceinline__ void mma8(float* c, const uint32_t* a, const uint32_t* b) {
    asm volatile(
        "mma.sync.aligned.m16n8k8.row.col.f32.tf32.tf32.f32 "
        "{%0,%1,%2,%3}, {%4,%5,%6,%7}, {%8,%9}, {%0,%1,%2,%3};"
        : "+f"(c[0]), "+f"(c[1]), "+f"(c[2]), "+f"(c[3])
        : "r"(a[0]), "r"(a[1]), "r"(a[2]), "r"(a[3]), "r"(b[0]), "r"(b[1]));
}

#define LDSM_X4(R0, R1, R2, R3, ADDR)                                        \
    asm volatile("ldmatrix.sync.aligned.m8n8.x4.shared.b16 {%0,%1,%2,%3}, [%4];" \
                 : "=r"(R0), "=r"(R1), "=r"(R2), "=r"(R3) : "r"(ADDR))

__device__ __forceinline__ void cp_async16(uint32_t dst, const void* src, int szbytes) {
    asm volatile("cp.async.cg.shared.global [%0], [%1], 16, %2;"
                 :: "r"(dst), "l"(src), "r"(szbytes));
}
#define CP_COMMIT() asm volatile("cp.async.commit_group;" ::: "memory")
#define CP_WAIT0() asm volatile("cp.async.wait_group 0;" ::: "memory")

// ---------------- weight pre-split kernels ----------------
__global__ void split_weights_kernel(const float* __restrict__ W,
                                     float* __restrict__ wh, float* __restrict__ wl,
                                     int K, int NC, int total) {
    int idx = blockIdx.x * 256 + threadIdx.x;
    if (idx >= total) return;
    int per = K * NC;
    int m = idx / per;
    int r = idx - m * per;
    int n = r / K;
    int k = r - n * K;
    float v = W[(size_t)m * per + (size_t)k * NC + n];
    uint32_t hi, lo;
    tf32_split(v, hi, lo);
    wh[idx] = __uint_as_float(hi);
    wl[idx] = __uint_as_float(lo);
}

__global__ void split_qkvo_kernel(const float* __restrict__ Wq, const float* __restrict__ Wk,
                                  const float* __restrict__ Wv, const float* __restrict__ Wo,
                                  float* __restrict__ wh, float* __restrict__ wl) {
    int idx = blockIdx.x * 256 + threadIdx.x;
    const int famSz = Ll * Dd * Dd;  // 98304
    if (idx >= 4 * famSz) return;
    int fam = idx / famSz;
    int r = idx - fam * famSz;
    int m = r / (Dd * Dd);
    int e = r - m * Dd * Dd;
    int n = e / Dd;
    int k = e - n * Dd;
    const float* W = fam == 0 ? Wq : (fam == 1 ? Wk : (fam == 2 ? Wv : Wo));
    float v = W[(size_t)m * Dd * Dd + (size_t)k * Dd + n];
    uint32_t hi, lo;
    tf32_split(v, hi, lo);
    wh[idx] = __uint_as_float(hi);
    wl[idx] = __uint_as_float(lo);
}

// ---------------- CSR build ----------------
__global__ void csr_zero_kernel() {
    int i = blockIdx.x * blockDim.x + threadIdx.x;
    if (i < Nn) {
        g_deg[i] = 0;
        g_cursor[i] = 0;
    }
}

__global__ void csr_hist_kernel(const int* __restrict__ ei) {
    int e = blockIdx.x * blockDim.x + threadIdx.x;
    if (e < Ee) atomicAdd(&g_deg[ei[Ee + e]], 1);
}

__global__ void csr_scan1_kernel() {
    __shared__ int sh[SCAN_B];
    int gi = blockIdx.x * SCAN_B + threadIdx.x;
    int v = (gi < Nn) ? g_deg[gi] : 0;
    sh[threadIdx.x] = v;
    __syncthreads();
#pragma unroll
    for (int off = 1; off < SCAN_B; off <<= 1) {
        int t = (threadIdx.x >= off) ? sh[threadIdx.x - off] : 0;
        __syncthreads();
        sh[threadIdx.x] += t;
        __syncthreads();
    }
    if (gi < Nn) g_scan[gi] = sh[threadIdx.x];
    if (threadIdx.x == SCAN_B - 1) g_bsum[blockIdx.x] = sh[threadIdx.x];
}

__global__ void csr_scan23_kernel() {
    __shared__ int soff;
    if (threadIdx.x == 0) {
        int acc = 0;
        for (int i = 0; i < (int)blockIdx.x; i++) acc += g_bsum[i];
        soff = acc;
    }
    __syncthreads();
    int gi = blockIdx.x * SCAN_B + threadIdx.x;
    if (gi < Nn) g_rowptr[gi + 1] = g_scan[gi] + soff;
    if (gi == 0) g_rowptr[0] = 0;
}

__global__ void csr_scatter_kernel(const int* __restrict__ ei) {
    int e = blockIdx.x * blockDim.x + threadIdx.x;
    if (e >= Ee) return;
    int src = ei[e], dst = ei[Ee + e];
    int pos = g_rowptr[dst] + atomicAdd(&g_cursor[dst], 1);
    g_col[pos] = src;
}

__global__ void zero_stats_kernel(double* __restrict__ a, double* __restrict__ b) {
    int t = threadIdx.x;
    if (t < Dd) {
        a[t] = 0.0;
        b[t] = 0.0;
    }
}

// ---------------- warp-mma tf32 GEMM: cp.async double-buffered ----------------
template <int K, int NC, bool BIAS, bool RELU, bool RES, bool BNA, bool BNRES,
          bool STATS, int NMAT>
__global__ __launch_bounds__(256, 2) void wm_gemm_kernel(
    const float* __restrict__ A,
    const float* __restrict__ wh, const float* __restrict__ wl,
    int off0, int off1, int off2,
    const float* __restrict__ bias, const float* __restrict__ res,
    const float* __restrict__ bng, const float* __restrict__ bnb,
    const double* __restrict__ bnsum, const double* __restrict__ bnsq,
    double* __restrict__ stsum, double* __restrict__ stsq,
    float* __restrict__ C0, float* __restrict__ C1, float* __restrict__ C2) {
    const int KC = 16;
    const int NCH = K / KC;
    const int YPM = NC / 128;
    constexpr int PSZ = BNA ? K : (BNRES ? 128 : 1);
    constexpr int SSZ = STATS ? 128 : 1;
    const int AP = 20;
    const int BP = 20;

    __shared__ float As[2][128 * AP];
    __shared__ uint32_t Bhs[2][128 * BP], Bls[2][128 * BP];
    __shared__ float s_sc[PSZ], s_sh[PSZ];
    __shared__ float s_cs[SSZ], s_cq[SSZ];

    int tid = threadIdx.x;
    int lane = tid & 31;
    int wid = tid >> 5;
    int wm = wid >> 1;
    int wn = wid & 1;
    int lr = lane >> 2;
    int lc = lane & 3;
    int rowBase = blockIdx.x * 128;
    int mat = (NMAT > 1) ? ((int)blockIdx.y / YPM) : 0;
    int colBase = ((int)blockIdx.y % YPM) * 128;
    size_t boff = (size_t)((NMAT > 1) ? (mat == 0 ? off0 : (mat == 1 ? off1 : off2)) : off0);
    float* C = (NMAT > 1) ? (mat == 0 ? C0 : (mat == 1 ? C1 : C2)) : C0;

    if (BNA || BNRES) {
        for (int c = tid; c < PSZ; c += 256) {
            double m = bnsum[c] / (double)Nn;
            double var = bnsq[c] / (double)Nn - m * m;
            float sc = rsqrtf((float)var + EPSf) * bng[c];
            s_sc[c] = sc;
            s_sh[c] = bnb[c] - (float)m * sc;
        }
    }
    if (STATS) {
        if (tid < SSZ) {
            s_cs[tid] = 0.f;
            s_cq[tid] = 0.f;
        }
    }

    float acc[2][8][4];
#pragma unroll
    for (int i = 0; i < 2; i++)
#pragma unroll
        for (int j = 0; j < 8; j++)
#pragma unroll
            for (int t = 0; t < 4; t++) acc[i][j][t] = 0.f;

    uint32_t asB[2], bhB[2], blB[2];
    asB[0] = (uint32_t)__cvta_generic_to_shared(&As[0][0]);
    asB[1] = (uint32_t)__cvta_generic_to_shared(&As[1][0]);
    bhB[0] = (uint32_t)__cvta_generic_to_shared(&Bhs[0][0]);
    bhB[1] = (uint32_t)__cvta_generic_to_shared(&Bhs[1][0]);
    blB[0] = (uint32_t)__cvta_generic_to_shared(&Bls[0][0]);
    blB[1] = (uint32_t)__cvta_generic_to_shared(&Bls[1][0]);

    const int aRow = (lane & 7) + ((lane >> 3) & 1) * 8;
    const int aK = ((lane >> 4) & 1) * 4;
    const int bRow = (lane & 7) + ((lane >> 4) & 1) * 8;
    const int bK = ((lane >> 3) & 1) * 4;
    const uint32_t aLane = (uint32_t)(((wm * 32 + aRow) * AP + aK) * 4);
    const uint32_t bLane = (uint32_t)(((wn * 64 + bRow) * BP + bK) * 4);

    auto fill = [&](int ch, int buf) {
        int kt = ch * KC;
#pragma unroll
        for (int l = 0; l < 2; l++) {
            int u = tid + 256 * l;
            int m_ = u >> 2;
            int kq = u & 3;
            int grow = rowBase + m_;
            bool valid = grow < Nn;
            const float* src = &A[(size_t)(valid ? grow : 0) * K + kt + kq * 4];
            cp_async16(asB[buf] + (uint32_t)((m_ * AP + kq * 4) * 4), src, valid ? 16 : 0);
        }
#pragma unroll
        for (int l = 0; l < 2; l++) {
            int u = tid + 256 * l;
            int n_ = u >> 2;
            int kq = u & 3;
            size_t goff = boff + (size_t)(colBase + n_) * K + kt + kq * 4;
            uint32_t doff = (uint32_t)((n_ * BP + kq * 4) * 4);
            cp_async16(bhB[buf] + doff, wh + goff, 16);
            cp_async16(blB[buf] + doff, wl + goff, 16);
        }
        CP_COMMIT();
    };

    fill(0, 0);
    CP_WAIT0();
    __syncthreads();
    int buf = 0;

    for (int ch = 0; ch < NCH; ch++) {
        bool hasNext = (ch + 1) < NCH;
        if (hasNext) fill(ch + 1, buf ^ 1);

        uint32_t aBase = asB[buf] + aLane;
        uint32_t bhBase = bhB[buf] + bLane;
        uint32_t blBase = blB[buf] + bLane;

#pragma unroll
        for (int kk = 0; kk < KC; kk += 8) {
            uint32_t ar_[2][4];
#pragma unroll
            for (int fm = 0; fm < 2; fm++) {
                uint32_t d = (uint32_t)((fm * 16 * AP + kk) * 4);
                LDSM_X4(ar_[fm][0], ar_[fm][1], ar_[fm][2], ar_[fm][3], aBase + d);
            }
            float sc0 = 1.f, sh0 = 0.f, sc4 = 1.f, sh4 = 0.f;
            if (BNA) {
                int kb = ch * KC + kk + lc;
                sc0 = s_sc[kb];
                sh0 = s_sh[kb];
                sc4 = s_sc[kb + 4];
                sh4 = s_sh[kb + 4];
            }
            uint32_t ah[2][4], al[2][4];
#pragma unroll
            for (int fm = 0; fm < 2; fm++)
#pragma unroll
                for (int j = 0; j < 4; j++) {
                    float v = __uint_as_float(ar_[fm][j]);
                    if (BNA) v = v * (j < 2 ? sc0 : sc4) + (j < 2 ? sh0 : sh4);
                    tf32_split(v, ah[fm][j], al[fm][j]);
                }
#pragma unroll
            for (int fnp = 0; fnp < 4; fnp++) {
                uint32_t bh[4], bl[4];
                uint32_t d = (uint32_t)((fnp * 16 * BP + kk) * 4);
                LDSM_X4(bh[0], bh[1], bh[2], bh[3], bhBase + d);
                LDSM_X4(bl[0], bl[1], bl[2], bl[3], blBase + d);
#pragma unroll
                for (int fm = 0; fm < 2; fm++) {
                    mma8(acc[fm][2 * fnp], ah[fm], &bh[0]);
                    mma8(acc[fm][2 * fnp], ah[fm], &bl[0]);
                    mma8(acc[fm][2 * fnp], al[fm], &bh[0]);
                    mma8(acc[fm][2 * fnp + 1], ah[fm], &bh[2]);
                    mma8(acc[fm][2 * fnp + 1], ah[fm], &bl[2]);
                    mma8(acc[fm][2 * fnp + 1], al[fm], &bh[2]);
                }
            }
        }

        if (hasNext) {
            CP_WAIT0();
            __syncthreads();
            buf ^= 1;
        }
    }

    // ---------------- epilogue ----------------
#pragma unroll
    for (int fm = 0; fm < 2; fm++) {
        int r0 = rowBase + wm * 32 + fm * 16 + lr;
        int r1 = r0 + 8;
        bool v0 = r0 < Nn, v1 = r1 < Nn;
#pragma unroll
        for (int fn = 0; fn < 8; fn++) {
            int cl = wn * 64 + fn * 8 + lc * 2;
            int gc = colBase + cl;
            float d0 = acc[fm][fn][0], d1 = acc[fm][fn][1];
            float d2 = acc[fm][fn][2], d3 = acc[fm][fn][3];
            if (BIAS) {
                float b0 = bias[gc], b1 = bias[gc + 1];
                d0 += b0; d1 += b1; d2 += b0; d3 += b1;
            }
            if (RES) {
                float sc0 = BNRES ? s_sc[cl] : 1.f, sh0 = BNRES ? s_sh[cl] : 0.f;
                float sc1 = BNRES ? s_sc[cl + 1] : 1.f, sh1 = BNRES ? s_sh[cl + 1] : 0.f;
                if (v0) {
                    float2 rv = *(const float2*)&res[(size_t)r0 * NC + gc];
                    d0 += rv.x * sc0 + sh0;
                    d1 += rv.y * sc1 + sh1;
                }
                if (v1) {
                    float2 rv = *(const float2*)&res[(size_t)r1 * NC + gc];
                    d2 += rv.x * sc0 + sh0;
                    d3 += rv.y * sc1 + sh1;
                }
            }
            if (RELU) {
                d0 = d0 > 0.f ? d0 : 0.f;
                d1 = d1 > 0.f ? d1 : 0.f;
                d2 = d2 > 0.f ? d2 : 0.f;
                d3 = d3 > 0.f ? d3 : 0.f;
            }
            if (STATS) {
                float e0 = v0 ? d0 : 0.f, e1 = v0 ? d1 : 0.f;
                float e2 = v1 ? d2 : 0.f, e3 = v1 ? d3 : 0.f;
                atomicAdd(&s_cs[cl], e0 + e2);
                atomicAdd(&s_cs[cl + 1], e1 + e3);
                atomicAdd(&s_cq[cl], e0 * e0 + e2 * e2);
                atomicAdd(&s_cq[cl + 1], e1 * e1 + e3 * e3);
            }
            if (v0) *(float2*)&C[(size_t)r0 * NC + gc] = make_float2(d0, d1);
            if (v1) *(float2*)&C[(size_t)r1 * NC + gc] = make_float2(d2, d3);
        }
    }

    if (STATS) {
        __syncthreads();
        if (tid < SSZ) {
            atomicAdd(&stsum[colBase + tid], (double)s_cs[tid]);
            atomicAdd(&stsq[colBase + tid], (double)s_cq[tid]);
        }
    }
}

// ---------------- fused edge attention: warp/dst, distance-1 prefetch ----------
__global__ __launch_bounds__(256) void attn_fused_kernel() {
    int warp = blockIdx.x * (blockDim.x >> 5) + (threadIdx.x >> 5);
    int lane = threadIdx.x & 31;
    if (warp >= Nn) return;
    int dst = warp;

    float4 q4 = *(const float4*)&g_q[dst * Dd + lane * 4];

    float m = -INFINITY;
    float l = 0.0f;
    float4 acc = make_float4(0.f, 0.f, 0.f, 0.f);

    int beg = g_rowptr[dst];
    int end = g_rowptr[dst + 1];

    // prefetch edge `beg`
    float4 kc = make_float4(0.f, 0.f, 0.f, 0.f);
    float4 vc = make_float4(0.f, 0.f, 0.f, 0.f);
    if (beg < end) {
        int s0 = __ldg(&g_col[beg]);
        kc = *(const float4*)&g_k[(size_t)s0 * Dd + lane * 4];
        vc = *(const float4*)&g_v[(size_t)s0 * Dd + lane * 4];
    }

    for (int j = beg; j < end; j++) {
        // issue next edge's loads BEFORE consuming the current one
        float4 kn, vn;
        int jn = j + 1;
        if (jn < end) {
            int s1 = __ldg(&g_col[jn]);
            kn = *(const float4*)&g_k[(size_t)s1 * Dd + lane * 4];
            vn = *(const float4*)&g_v[(size_t)s1 * Dd + lane * 4];
        }

        float p = q4.x * kc.x + q4.y * kc.y + q4.z * kc.z + q4.w * kc.w;
        p += __shfl_xor_sync(0xffffffffu, p, 1);
        p += __shfl_xor_sync(0xffffffffu, p, 2);
        float s = p * 0.25f;

        float newm = fmaxf(m, s);
        float corr = __expf(m - newm);
        float pe = __expf(s - newm);
        acc.x = acc.x * corr + pe * vc.x;
        acc.y = acc.y * corr + pe * vc.y;
        acc.z = acc.z * corr + pe * vc.z;
        acc.w = acc.w * corr + pe * vc.w;
        l = l * corr + pe;
        m = newm;

        if (jn < end) {
            kc = kn;
            vc = vn;
        }
    }
    float inv = (l > 0.f) ? (1.0f / l) : 0.0f;
    acc.x *= inv; acc.y *= inv; acc.z *= inv; acc.w *= inv;
    *(float4*)&g_attn[dst * Dd + lane * 4] = acc;
}

// ---------------- final projection (with fused BN on input) ----------------
__global__ void proj_kernel(const float* __restrict__ Wp, const float* __restrict__ bp,
                            const float* __restrict__ bng, const float* __restrict__ bnb,
                            float* __restrict__ out) {
    int warp = blockIdx.x * (blockDim.x >> 5) + (threadIdx.x >> 5);
    int lane = threadIdx.x & 31;
    if (warp >= Nn) return;

    float sc[4], sh[4];
#pragma unroll
    for (int i = 0; i < 4; i++) {
        int c = lane + 32 * i;
        double m = g_sum2[c] / (double)Nn;
        double var = g_sq2[c] / (double)Nn - m * m;
        float s = rsqrtf((float)var + EPSf) * bng[c];
        sc[i] = s;
        sh[i] = bnb[c] - (float)m * s;
    }

    float acc[Cc] = {0.f, 0.f, 0.f, 0.f, 0.f};
#pragma unroll
    for (int i = 0; i < 4; i++) {
        int k = lane + 32 * i;
        float xv = g_tmp2[warp * Dd + k] * sc[i] + sh[i];
#pragma unroll
        for (int c = 0; c < Cc; c++) acc[c] += xv * Wp[k * Cc + c];
    }
#pragma unroll
    for (int c = 0; c < Cc; c++) {
#pragma unroll
        for (int o = 16; o > 0; o >>= 1) acc[c] += __shfl_down_sync(0xffffffffu, acc[c], o);
    }
    if (lane == 0) {
#pragma unroll
        for (int c = 0; c < Cc; c++) out[warp * Cc + c] = acc[c] + bp[c];
    }
}

// ---------------- launch ----------------
extern "C" void kernel_launch(void* const* d_in, const int* in_sizes, int n_in,
                              void* d_out, int out_size) {
    const float* x   = (const float*)d_in[0];
    const int*   ei  = (const int*)d_in[1];
    const float* Wq  = (const float*)d_in[2];
    const float* Wk  = (const float*)d_in[3];
    const float* Wv  = (const float*)d_in[4];
    const float* Wo  = (const float*)d_in[5];
    const float* g1  = (const float*)d_in[6];
    const float* bn1 = (const float*)d_in[7];
    const float* W1  = (const float*)d_in[8];
    const float* bf1 = (const float*)d_in[9];
    const float* W2  = (const float*)d_in[10];
    const float* bf2 = (const float*)d_in[11];
    const float* g2  = (const float*)d_in[12];
    const float* bn2 = (const float*)d_in[13];
    const float* Wp  = (const float*)d_in[14];
    const float* bp  = (const float*)d_in[15];
    float* out = (float*)d_out;

    float *pq, *pk, *pv, *pattn, *ptmp1, *ptmp2, *pff, *pwh, *pwl;
    double *psum1, *psq1, *psum2, *psq2;
    cudaGetSymbolAddress((void**)&pq, g_q);
    cudaGetSymbolAddress((void**)&pk, g_k);
    cudaGetSymbolAddress((void**)&pv, g_v);
    cudaGetSymbolAddress((void**)&pattn, g_attn);
    cudaGetSymbolAddress((void**)&ptmp1, g_tmp1);
    cudaGetSymbolAddress((void**)&ptmp2, g_tmp2);
    cudaGetSymbolAddress((void**)&pff, g_ff);
    cudaGetSymbolAddress((void**)&pwh, g_wh);
    cudaGetSymbolAddress((void**)&pwl, g_wl);
    cudaGetSymbolAddress((void**)&psum1, g_sum1);
    cudaGetSymbolAddress((void**)&psq1, g_sq1);
    cudaGetSymbolAddress((void**)&psum2, g_sum2);
    cudaGetSymbolAddress((void**)&psq2, g_sq2);

    const int gemmRows = (Nn + 127) / 128;  // 391
    const int edgeBlocks = (Ee + 255) / 256;
    const int nodeBlocks = (Nn + 255) / 256;
    const int warpBlocks = (Nn + 7) / 8;

    csr_zero_kernel<<<nodeBlocks, 256>>>();
    csr_hist_kernel<<<edgeBlocks, 256>>>(ei);
    split_qkvo_kernel<<<(4 * Ll * Dd * Dd + 255) / 256, 256>>>(Wq, Wk, Wv, Wo,
                                                               pwh, pwl);
    // #4: layer-0 QKV (profiled launch — control, should stay ~79 μs)
    wm_gemm_kernel<Dd, Dd, false, false, false, false, false, false, 3>
        <<<dim3(gemmRows, 3), 256>>>(x, pwh, pwl,
                                     OFF_WQ, OFF_WK, OFF_WV,
                                     nullptr, nullptr, nullptr, nullptr,
                                     nullptr, nullptr, nullptr, nullptr,
                                     pq, pk, pv);
    split_weights_kernel<<<(Ll * Dd * FFd + 255) / 256, 256>>>(
        W1, pwh + OFF_W1, pwl + OFF_W1, Dd, FFd, Ll * Dd * FFd);
    split_weights_kernel<<<(Ll * FFd * Dd + 255) / 256, 256>>>(
        W2, pwh + OFF_W2, pwl + OFF_W2, FFd, Dd, Ll * FFd * Dd);
    csr_scan1_kernel<<<SCAN_NB, SCAN_B>>>();
    csr_scan23_kernel<<<SCAN_NB, SCAN_B>>>();
    csr_scatter_kernel<<<edgeBlocks, 256>>>(ei);

    for (int i = 0; i < Ll; i++) {
        if (i > 0) {
            wm_gemm_kernel<Dd, Dd, false, false, false, true, false, false, 3>
                <<<dim3(gemmRows, 3), 256>>>(
                    ptmp2, pwh, pwl,
                    OFF_WQ + i * 16384, OFF_WK + i * 16384, OFF_WV + i * 16384,
                    nullptr, nullptr,
                    g2 + (i - 1) * Dd, bn2 + (i - 1) * Dd,
                    psum2, psq2, nullptr, nullptr, pq, pk, pv);
        }

        attn_fused_kernel<<<warpBlocks, 256>>>();

        zero_stats_kernel<<<1, 128>>>(psum1, psq1);

        if (i == 0) {
            wm_gemm_kernel<Dd, Dd, false, false, true, false, false, true, 1>
                <<<dim3(gemmRows, 1), 256>>>(
                    pattn, pwh, pwl, OFF_WO, 0, 0,
                    nullptr, x, nullptr, nullptr, nullptr, nullptr,
                    psum1, psq1, ptmp1, nullptr, nullptr);
        } else {
            wm_gemm_kernel<Dd, Dd, false, false, true, false, true, true, 1>
                <<<dim3(gemmRows, 1), 256>>>(
                    pattn, pwh, pwl, OFF_WO + i * 16384, 0, 0,
                    nullptr, ptmp2,
                    g2 + (i - 1) * Dd, bn2 + (i - 1) * Dd,
                    psum2, psq2, psum1, psq1, ptmp1, nullptr, nullptr);
        }

        wm_gemm_kernel<Dd, FFd, true, true, false, true, false, false, 1>
            <<<dim3(gemmRows, 2), 256>>>(
                ptmp1, pwh, pwl, OFF_W1 + i * 32768, 0, 0,
                bf1 + i * FFd, nullptr,
                g1 + i * Dd, bn1 + i * Dd,
                psum1, psq1, nullptr, nullptr, pff, nullptr, nullptr);

        zero_stats_kernel<<<1, 128>>>(psum2, psq2);

        wm_gemm_kernel<FFd, Dd, true, false, true, false, true, true, 1>
            <<<dim3(gemmRows, 1), 256>>>(
                pff, pwh, pwl, OFF_W2 + i * 32768, 0, 0,
                bf2 + i * Dd, ptmp1,
                g1 + i * Dd, bn1 + i * Dd,
                psum1, psq1, psum2, psq2, ptmp2, nullptr, nullptr);
    }

    proj_kernel<<<warpBlocks, 256>>>(Wp, bp, g2 + (Ll - 1) * Dd, bn2 + (Ll - 1) * Dd, out);
}